// round 17
// baseline (speedup 1.0000x reference)
#include <cuda_runtime.h>
#include <cuda_bf16.h>
#include <math.h>
#include <stdint.h>

#define S_LEN  2048
#define DMODEL 1024
#define NHEADS 16
#define DK     64
#define BATCH  2
#define MROWS  (BATCH * S_LEN)   // 4096

// qk scale 1/8 folded with log2(e) into Q, so softmax uses exp2
#define QSCALE 0.18033688011112042f   // 0.125 * log2(e)

// ---------------------------------------------------------------------------
// Device-global scratch. Split layout per 32-col block: [16 u32 hi | 16 u32 mid]
// (bf16x2 per u32, pair = adjacent columns)
// ---------------------------------------------------------------------------
__device__ uint32_t g_Xs[MROWS * DMODEL];              // x split
__device__ uint32_t g_Ws[4][DMODEL * DMODEL];          // Wq,Wk,Wv,Wo split
__device__ uint32_t g_Qs[BATCH * NHEADS * S_LEN * 64]; // Q split (row: 32 hi|32 mid)
__device__ uint32_t g_Ks[BATCH * NHEADS * S_LEN * 64]; // K split
__device__ uint32_t g_Vts[BATCH * NHEADS * DK * (S_LEN / 2) * 2]; // V^T split (b,h,d,s)
__device__ uint32_t g_Os[MROWS * DMODEL];              // attention out, split

// ===========================================================================
// PTX helpers
// ===========================================================================
__device__ __forceinline__ uint32_t smem_u32(const void* p) {
    uint32_t a;
    asm("{ .reg .u64 t; cvta.to.shared.u64 t, %1; cvt.u32.u64 %0, t; }"
        : "=r"(a) : "l"(p));
    return a;
}
__device__ __forceinline__ void cp_async16(uint32_t dst, const void* src) {
    asm volatile("cp.async.cg.shared.global [%0], [%1], 16;"
                 :: "r"(dst), "l"(src));
}
#define CP_COMMIT() asm volatile("cp.async.commit_group;" ::: "memory")
#define CP_WAIT1()  asm volatile("cp.async.wait_group 1;" ::: "memory")
#define CP_WAIT0()  asm volatile("cp.async.wait_group 0;" ::: "memory")

#define LDSM_X4(r0, r1, r2, r3, addr)                                     \
    asm volatile("ldmatrix.sync.aligned.m8n8.x4.shared.b16 "              \
                 "{%0,%1,%2,%3}, [%4];"                                   \
                 : "=r"(r0), "=r"(r1), "=r"(r2), "=r"(r3) : "r"(addr))

#define MMA_BF16(c, a, b0, b1)                                            \
    asm volatile("mma.sync.aligned.m16n8k16.row.col.f32.bf16.bf16.f32 "   \
                 "{%0,%1,%2,%3},{%4,%5,%6,%7},{%8,%9},{%0,%1,%2,%3};"     \
                 : "+f"((c)[0]), "+f"((c)[1]), "+f"((c)[2]), "+f"((c)[3]) \
                 : "r"((a)[0]), "r"((a)[1]), "r"((a)[2]), "r"((a)[3]),    \
                   "r"(b0), "r"(b1))

__device__ __forceinline__ void bf16_split2(float x0, float x1,
                                            uint32_t& hi2, uint32_t& mid2) {
    uint32_t h;
    asm("cvt.rn.bf16x2.f32 %0, %2, %1;" : "=r"(h) : "f"(x0), "f"(x1));
    float h0 = __uint_as_float(h << 16);
    float h1 = __uint_as_float(h & 0xffff0000u);
    float m0 = x0 - h0, m1 = x1 - h1;
    uint32_t m;
    asm("cvt.rn.bf16x2.f32 %0, %2, %1;" : "=r"(m) : "f"(m0), "f"(m1));
    hi2 = h; mid2 = m;
}

// ===========================================================================
// Fused split prep: x and the four weight matrices in one launch.
// ===========================================================================
__global__ __launch_bounds__(256) void split_all_kernel(
    const float* __restrict__ x,  const float* __restrict__ Wq,
    const float* __restrict__ Wk, const float* __restrict__ Wv,
    const float* __restrict__ Wo)
{
    int idx = blockIdx.x * 256 + threadIdx.x;   // one per 4-float group
    int r   = idx >> 8;
    int p4  = idx & 255;
    const float* src;
    uint32_t*    dstrow;
    if (r < MROWS) {
        src    = x    + ((size_t)r << 10);
        dstrow = g_Xs + ((size_t)r << 10);
    } else {
        int rr = r - MROWS;
        int w  = rr >> 10;
        int wr = rr & 1023;
        const float* ws = (w == 0) ? Wq : (w == 1) ? Wk : (w == 2) ? Wv : Wo;
        src    = ws + ((size_t)wr << 10);
        dstrow = g_Ws[w] + ((size_t)wr << 10);
    }
    int kb = p4 >> 3, q = p4 & 7;
    float4 v = *(const float4*)(src + p4 * 4);
    uint32_t h0, m0, h1, m1;
    bf16_split2(v.x, v.y, h0, m0);
    bf16_split2(v.z, v.w, h1, m1);
    uint32_t* o = dstrow + kb * 32;
    *(uint2*)(o + 2 * q)      = make_uint2(h0, h1);
    *(uint2*)(o + 16 + 2 * q) = make_uint2(m0, m1);
}

// ===========================================================================
// 3xBF16 GEMM, 3-stage cp.async ring.
// mode 0=Q (RoPE*scale + split bhsd), 1=K (RoPE + split bhsd),
// 2=V (transpose + split -> g_Vts, fused, no g_V round trip),
// 3=O-proj (f32 row-major out)
// ===========================================================================
__global__ __launch_bounds__(256) void mma_gemm_kernel(
    const int* __restrict__ pos,
    float*     __restrict__ outp,
    int mode_sel)
{
    extern __shared__ char dynsmem[];

    const int mode = (mode_sel < 0) ? (int)blockIdx.z : mode_sel;
    const uint32_t* __restrict__ A = (mode == 3) ? g_Os : g_Xs;
    const uint32_t* __restrict__ W = g_Ws[mode];

    const int t   = threadIdx.x;
    const int wid = t >> 5;
    const int lid = t & 31;
    const int wm  = wid >> 2;
    const int wn  = wid & 3;
    const int n0  = blockIdx.x * 128;
    const int m0  = blockIdx.y * 128;

    uint32_t raw = smem_u32(dynsmem);
    uint32_t pad = (1024u - (raw & 1023u)) & 1023u;
    const uint32_t sbase = raw + pad;

    float c[4][4][4];
#pragma unroll
    for (int i = 0; i < 4; i++)
#pragma unroll
        for (int j = 0; j < 4; j++)
#pragma unroll
            for (int k = 0; k < 4; k++) c[i][j][k] = 0.f;

    auto stage_load = [&](int buf, int s) {
        const uint32_t sa = sbase + buf * 32768;
#pragma unroll
        for (int i = 0; i < 4; i++) {
            int idx = i * 256 + t;
            int row = idx >> 3;
            int ch  = idx & 7;
            uint32_t off = (uint32_t)(row * 128 + ((ch ^ (row & 7)) << 4));
            cp_async16(sa + off,         A + (size_t)(m0 + row) * 1024 + s * 32 + ch * 4);
            cp_async16(sa + 16384 + off, W + (size_t)(n0 + row) * 1024 + s * 32 + ch * 4);
        }
        CP_COMMIT();
    };

    stage_load(0, 0);
    stage_load(1, 1);

    int buf = 0;
    for (int s = 0; s < 32; s++) {
        if (s == 31) { CP_WAIT0(); } else { CP_WAIT1(); }
        __syncthreads();
        if (s + 2 < 32) {
            int nb = buf + 2; if (nb >= 3) nb -= 3;
            stage_load(nb, s + 2);
        }

        const uint32_t As_a = sbase + buf * 32768;
        const uint32_t Bs_a = As_a + 16384;

#pragma unroll
        for (int kc = 0; kc < 2; kc++) {
            uint32_t bhf[2][4], bmf[2][4];
#pragma unroll
            for (int ng = 0; ng < 2; ng++) {
                int row = wn * 32 + ng * 16 + ((lid >> 4) << 3) + (lid & 7);
                int ch  = 2 * kc + ((lid >> 3) & 1);
                uint32_t rb = Bs_a + row * 128;
                LDSM_X4(bhf[ng][0], bhf[ng][1], bhf[ng][2], bhf[ng][3],
                        rb + ((ch ^ (row & 7)) << 4));
                LDSM_X4(bmf[ng][0], bmf[ng][1], bmf[ng][2], bmf[ng][3],
                        rb + (((ch + 4) ^ (row & 7)) << 4));
            }
#pragma unroll
            for (int mi = 0; mi < 4; mi++) {
                int row = wm * 64 + mi * 16 + (lid & 15);
                int ch  = 2 * kc + (lid >> 4);
                uint32_t ra = As_a + row * 128;
                uint32_t ah[4], am[4];
                LDSM_X4(ah[0], ah[1], ah[2], ah[3], ra + ((ch ^ (row & 7)) << 4));
                LDSM_X4(am[0], am[1], am[2], am[3], ra + (((ch + 4) ^ (row & 7)) << 4));
#pragma unroll
                for (int ng = 0; ng < 2; ng++) {
                    MMA_BF16(c[mi][2 * ng],     am, bhf[ng][0], bhf[ng][1]);
                    MMA_BF16(c[mi][2 * ng],     ah, bmf[ng][0], bmf[ng][1]);
                    MMA_BF16(c[mi][2 * ng],     ah, bhf[ng][0], bhf[ng][1]);
                    MMA_BF16(c[mi][2 * ng + 1], am, bhf[ng][2], bhf[ng][3]);
                    MMA_BF16(c[mi][2 * ng + 1], ah, bmf[ng][2], bmf[ng][3]);
                    MMA_BF16(c[mi][2 * ng + 1], ah, bhf[ng][2], bhf[ng][3]);
                }
            }
        }
        buf++; if (buf >= 3) buf -= 3;
    }

    // ---------------- epilogue ----------------
    const int rbase = m0 + wm * 64 + (lid >> 2);
    const int cbase = n0 + wn * 32 + (lid & 3) * 2;
    const float neg_lt = -logf(10000.0f) / 64.0f;

    if (mode == 3) {
#pragma unroll
        for (int mi = 0; mi < 4; mi++) {
#pragma unroll
            for (int nj = 0; nj < 4; nj++) {
                int row0 = rbase + mi * 16;
                int col  = cbase + nj * 8;
                *(float2*)(outp + (size_t)row0 * DMODEL + col) =
                    make_float2(c[mi][nj][0], c[mi][nj][1]);
                *(float2*)(outp + (size_t)(row0 + 8) * DMODEL + col) =
                    make_float2(c[mi][nj][2], c[mi][nj][3]);
            }
        }
    } else if (mode == 2) {
        // V: transpose in smem, split, write g_Vts directly (vts fused)
        float* sT = (float*)(dynsmem + pad);   // [128 cols][132] f32 = 67.6KB
        __syncthreads();   // mainloop reads of stage buffers complete
#pragma unroll
        for (int mi = 0; mi < 4; mi++) {
            int lrow0 = wm * 64 + mi * 16 + (lid >> 2);
#pragma unroll
            for (int nj = 0; nj < 4; nj++) {
                int lcol = wn * 32 + nj * 8 + 2 * (lid & 3);
                sT[(size_t)lcol * 132 + lrow0]           = c[mi][nj][0];
                sT[(size_t)(lcol + 1) * 132 + lrow0]     = c[mi][nj][1];
                sT[(size_t)lcol * 132 + lrow0 + 8]       = c[mi][nj][2];
                sT[(size_t)(lcol + 1) * 132 + lrow0 + 8] = c[mi][nj][3];
            }
        }
        __syncthreads();
        const int lc  = t >> 1;                  // local col 0..127
        const int hh  = (n0 + lc) >> 6;
        const int dg  = (n0 + lc) & 63;
        const int bb  = m0 >> 11;
        const int bhh = bb * NHEADS + hh;
        const int sblk0 = (m0 & (S_LEN - 1)) >> 5;
        uint32_t* dstbase = g_Vts + (size_t)bhh * 64 * 2048 + (size_t)dg * 2048;
#pragma unroll
        for (int sb = 0; sb < 2; sb++) {
            int blk = (t & 1) * 2 + sb;          // 0..3 (32-s block within tile)
            const float* srcp = sT + (size_t)lc * 132 + blk * 32;
            uint32_t hi[16], mid[16];
#pragma unroll
            for (int j = 0; j < 16; j++)
                bf16_split2(srcp[2 * j], srcp[2 * j + 1], hi[j], mid[j]);
            uint32_t* dst = dstbase + (sblk0 + blk) * 32;
#pragma unroll
            for (int j = 0; j < 16; j += 4) {
                *(uint4*)(dst + j)      = make_uint4(hi[j], hi[j+1], hi[j+2], hi[j+3]);
                *(uint4*)(dst + 16 + j) = make_uint4(mid[j], mid[j+1], mid[j+2], mid[j+3]);
            }
        }
    } else {
        uint32_t* basep = (mode == 0) ? g_Qs : g_Ks;
        const float osc = (mode == 0) ? QSCALE : 1.0f;
#pragma unroll
        for (int mi = 0; mi < 4; mi++) {
#pragma unroll
            for (int half = 0; half < 2; half++) {
                int row  = rbase + mi * 16 + half * 8;
                int b    = row >> 11;
                int srow = row & (S_LEN - 1);
                float p  = (float)pos[srow];
#pragma unroll
                for (int nj = 0; nj < 4; nj++) {
                    int col = cbase + nj * 8;
                    int h   = col >> 6;
                    int d   = col & 63;
                    float x1 = c[mi][nj][half * 2];
                    float x2 = c[mi][nj][half * 2 + 1];
                    float fr = expf((float)d * neg_lt);
                    float sn, cs;
                    sincosf(p * fr, &sn, &cs);
                    float r1 = (x1 * cs - x2 * sn) * osc;
                    float r2 = (x1 * sn + x2 * cs) * osc;
                    uint32_t hi, mid;
                    bf16_split2(r1, r2, hi, mid);
                    uint32_t* dst = basep +
                        ((size_t)(b * NHEADS + h) * S_LEN + srow) * 64;
                    dst[d >> 1]        = hi;
                    dst[32 + (d >> 1)] = mid;
                }
            }
        }
    }
}

// ===========================================================================
// 3xBF16 flash attention (causal). CTA: 128 q-rows of one (b,h); 8 warps.
// Grid: x = bh (32), y = q-tile issued LARGEST-FIRST (LPT scheduling).
// Fully-masked kv fragment groups are skipped per warp on crossing tiles.
// ===========================================================================
__global__ __launch_bounds__(256, 2) void attn_mma_kernel()
{
    extern __shared__ char dynsmem[];

    const int t   = threadIdx.x;
    const int wid = t >> 5;
    const int lid = t & 31;
    const int bh  = blockIdx.x;
    const int q0  = (int)(gridDim.y - 1 - blockIdx.y) * 128;  // big CTAs first
    const int b   = bh >> 4;
    const int h   = bh & 15;

    const uint32_t* __restrict__ Qg  = g_Qs  + (size_t)bh * S_LEN * 64;
    const uint32_t* __restrict__ Kg  = g_Ks  + (size_t)bh * S_LEN * 64;
    const uint32_t* __restrict__ Vtg = g_Vts + (size_t)bh * 64 * 2048;

    uint32_t raw = smem_u32(dynsmem);
    uint32_t pad = (1024u - (raw & 1023u)) & 1023u;
    const uint32_t sQ = raw + pad;
    const uint32_t sKb[2] = {sQ + 32768, sQ + 49152};
    const uint32_t sVb[2] = {sQ + 65536, sQ + 81920};

    auto load_k = [&](uint32_t sdst, int kv0) {
#pragma unroll
        for (int i = 0; i < 4; i++) {
            int idx = i * 256 + t, row = idx >> 4, ch = idx & 15;
            cp_async16(sdst + row * 256 + (ch & 8) * 16 +
                           (((ch & 7) ^ (row & 7)) << 4),
                       Kg + (size_t)(kv0 + row) * 64 + ch * 4);
        }
    };
    auto load_v = [&](uint32_t sdst, int kv0) {
#pragma unroll
        for (int i = 0; i < 4; i++) {
            int idx = i * 256 + t, d = idx >> 4, ch = idx & 15;
            int g = ch >> 2, bq = ch & 3;
            int chd = (((g << 1) | (g >> 1)) & 3) * 4 + bq;
            cp_async16(sdst + d * 256 + (chd & 8) * 16 +
                           (((chd & 7) ^ (d & 7)) << 4),
                       Vtg + (size_t)d * 2048 + kv0 + ch * 4);
        }
    };

    // prologue: Q + tile0 (group 0), tile1 (group 1)
#pragma unroll
    for (int i = 0; i < 8; i++) {
        int idx = i * 256 + t, row = idx >> 4, ch = idx & 15;
        cp_async16(sQ + row * 256 + (ch & 8) * 16 +
                       (((ch & 7) ^ (row & 7)) << 4),
                   Qg + (size_t)(q0 + row) * 64 + ch * 4);
    }
    load_k(sKb[0], 0);
    load_v(sVb[0], 0);
    CP_COMMIT();
    const int ntiles = (q0 >> 6) + 2;   // always >= 2
    load_k(sKb[1], 64);
    load_v(sVb[1], 64);
    CP_COMMIT();
    CP_WAIT1();
    __syncthreads();

    float o[8][4];
#pragma unroll
    for (int i = 0; i < 8; i++)
#pragma unroll
        for (int j = 0; j < 4; j++) o[i][j] = 0.f;
    float mrow[2] = {-1e30f, -1e30f};
    float lrow[2] = {0.f, 0.f};

    const int wq_min = q0 + 16 * wid;
    const int wq_max = wq_min + 15;

    for (int kt = 0; kt < ntiles; kt++) {
        const int k0 = kt * 64;
        const uint32_t sKc = sKb[kt & 1];
        const uint32_t sVc = sVb[kt & 1];

        if (k0 <= wq_max) {
            // ---- S = Q K^T (3xBF16), Q pre-scaled by 0.125*log2e ----
            float s[8][4];
#pragma unroll
            for (int i = 0; i < 8; i++)
#pragma unroll
                for (int j = 0; j < 4; j++) s[i][j] = 0.f;

#pragma unroll
            for (int kc = 0; kc < 4; kc++) {
                int rowa = 16 * wid + (lid & 15);
                int cha  = 2 * kc + (lid >> 4);
                uint32_t ra = sQ + rowa * 256;
                uint32_t ah[4], am[4];
                LDSM_X4(ah[0], ah[1], ah[2], ah[3],
                        ra + ((cha ^ (rowa & 7)) << 4));
                LDSM_X4(am[0], am[1], am[2], am[3],
                        ra + 128 + ((cha ^ (rowa & 7)) << 4));
#pragma unroll
                for (int ng = 0; ng < 4; ng++) {
                    if (k0 + 16 * ng > wq_max) continue;  // fully masked cols
                    int rowb = ng * 16 + ((lid >> 4) << 3) + (lid & 7);
                    int chb  = 2 * kc + ((lid >> 3) & 1);
                    uint32_t rb = sKc + rowb * 256;
                    uint32_t bhf[4], bmf[4];
                    LDSM_X4(bhf[0], bhf[1], bhf[2], bhf[3],
                            rb + ((chb ^ (rowb & 7)) << 4));
                    LDSM_X4(bmf[0], bmf[1], bmf[2], bmf[3],
                            rb + 128 + ((chb ^ (rowb & 7)) << 4));
                    MMA_BF16(s[2 * ng],     am, bhf[0], bhf[1]);
                    MMA_BF16(s[2 * ng],     ah, bmf[0], bmf[1]);
                    MMA_BF16(s[2 * ng],     ah, bhf[0], bhf[1]);
                    MMA_BF16(s[2 * ng + 1], am, bhf[2], bhf[3]);
                    MMA_BF16(s[2 * ng + 1], ah, bmf[2], bmf[3]);
                    MMA_BF16(s[2 * ng + 1], ah, bhf[2], bhf[3]);
                }
            }

            // ---- causal mask (whenever tile passes warp's first q row) ----
            const int qA = q0 + 16 * wid + (lid >> 2);
            if (k0 + 63 > wq_min) {
#pragma unroll
                for (int nf = 0; nf < 8; nf++) {
                    int colb = k0 + nf * 8 + 2 * (lid & 3);
#pragma unroll
                    for (int e = 0; e < 4; e++) {
                        int q  = qA + ((e >> 1) << 3);
                        int kv = colb + (e & 1);
                        if (kv > q) s[nf][e] = -1e30f;
                    }
                }
            }

            // ---- online softmax (log2 domain) ----
#pragma unroll
            for (int half = 0; half < 2; half++) {
                float ml = -1e30f;
#pragma unroll
                for (int nf = 0; nf < 8; nf++)
                    ml = fmaxf(ml, fmaxf(s[nf][2 * half], s[nf][2 * half + 1]));
                ml = fmaxf(ml, __shfl_xor_sync(0xffffffffu, ml, 1));
                ml = fmaxf(ml, __shfl_xor_sync(0xffffffffu, ml, 2));
                float mn = fmaxf(mrow[half], ml);
                float al = exp2f(mrow[half] - mn);
                mrow[half] = mn;
                float ls = 0.f;
#pragma unroll
                for (int nf = 0; nf < 8; nf++) {
                    float e0 = exp2f(s[nf][2 * half] - mn);
                    float e1 = exp2f(s[nf][2 * half + 1] - mn);
                    s[nf][2 * half] = e0;
                    s[nf][2 * half + 1] = e1;
                    ls += e0 + e1;
                }
                ls += __shfl_xor_sync(0xffffffffu, ls, 1);
                ls += __shfl_xor_sync(0xffffffffu, ls, 2);
                lrow[half] = lrow[half] * al + ls;
#pragma unroll
                for (int nf = 0; nf < 8; nf++) {
                    o[nf][2 * half] *= al;
                    o[nf][2 * half + 1] *= al;
                }
            }

            // ---- O += P V : P -> A-fragments in registers; skip kv-chunks
            //      that are fully masked (P == 0 there) ----
#pragma unroll
            for (int kc = 0; kc < 4; kc++) {
                if (k0 + 16 * kc > wq_max) continue;
                uint32_t ph[4], pm[4];
                bf16_split2(s[2 * kc][0],     s[2 * kc][1],     ph[0], pm[0]);
                bf16_split2(s[2 * kc][2],     s[2 * kc][3],     ph[1], pm[1]);
                bf16_split2(s[2 * kc + 1][0], s[2 * kc + 1][1], ph[2], pm[2]);
                bf16_split2(s[2 * kc + 1][2], s[2 * kc + 1][3], ph[3], pm[3]);
#pragma unroll
                for (int ng = 0; ng < 4; ng++) {
                    int rowb = ng * 16 + ((lid >> 4) << 3) + (lid & 7);
                    int chb  = 2 * kc + ((lid >> 3) & 1);
                    uint32_t rb = sVc + rowb * 256;
                    uint32_t vh[4], vm[4];
                    LDSM_X4(vh[0], vh[1], vh[2], vh[3],
                            rb + ((chb ^ (rowb & 7)) << 4));
                    LDSM_X4(vm[0], vm[1], vm[2], vm[3],
                            rb + 128 + ((chb ^ (rowb & 7)) << 4));
                    MMA_BF16(o[2 * ng],     pm, vh[0], vh[1]);
                    MMA_BF16(o[2 * ng],     ph, vm[0], vm[1]);
                    MMA_BF16(o[2 * ng],     ph, vh[0], vh[1]);
                    MMA_BF16(o[2 * ng + 1], pm, vh[2], vh[3]);
                    MMA_BF16(o[2 * ng + 1], ph, vm[2], vm[3]);
                    MMA_BF16(o[2 * ng + 1], ph, vh[2], vh[3]);
                }
            }
        }

        __syncthreads();   // all warps done with buffers of tile kt
        bool more = (kt + 2 < ntiles);
        if (more) {
            load_k(sKb[kt & 1], (kt + 2) * 64);
            load_v(sVb[kt & 1], (kt + 2) * 64);
            CP_COMMIT();
        }
        if (kt + 1 < ntiles) {
            if (more) { CP_WAIT1(); } else { CP_WAIT0(); }
            __syncthreads();
        }
    }

    // ---- normalize + write split rows into g_Os ----
    const float i0 = 1.0f / lrow[0];
    const float i1 = 1.0f / lrow[1];
    const int qA = q0 + 16 * wid + (lid >> 2);
    const size_t row0 = (size_t)(b * S_LEN + qA) * 1024;
    const size_t row1 = (size_t)(b * S_LEN + qA + 8) * 1024;
#pragma unroll
    for (int nf = 0; nf < 8; nf++) {
        int col = h * 64 + nf * 8 + 2 * (lid & 3);
        int kb = col >> 5;
        int jj = (col & 31) >> 1;
        uint32_t hi, mid;
        bf16_split2(o[nf][0] * i0, o[nf][1] * i0, hi, mid);
        g_Os[row0 + kb * 32 + jj]      = hi;
        g_Os[row0 + kb * 32 + 16 + jj] = mid;
        bf16_split2(o[nf][2] * i1, o[nf][3] * i1, hi, mid);
        g_Os[row1 + kb * 32 + jj]      = hi;
        g_Os[row1 + kb * 32 + 16 + jj] = mid;
    }
}

// ---------------------------------------------------------------------------
extern "C" void kernel_launch(void* const* d_in, const int* in_sizes, int n_in,
                              void* d_out, int out_size)
{
    const float* x   = (const float*)d_in[0];
    const int*   pos = (const int*)  d_in[1];
    const float* Wq  = (const float*)d_in[2];
    const float* Wk  = (const float*)d_in[3];
    const float* Wv  = (const float*)d_in[4];
    const float* Wo  = (const float*)d_in[5];
    float* out = (float*)d_out;

    const int DYN_GEMM = 3 * 32768 + 1024;
    const int DYN_ATTN = 98304 + 1024;
    cudaFuncSetAttribute(mma_gemm_kernel,
                         cudaFuncAttributeMaxDynamicSharedMemorySize, DYN_GEMM);
    cudaFuncSetAttribute(attn_mma_kernel,
                         cudaFuncAttributeMaxDynamicSharedMemorySize, DYN_ATTN);

    // Fused split prep (x + 4 weights)
    split_all_kernel<<<MROWS + 4 * DMODEL, 256>>>(x, Wq, Wk, Wv, Wo);

    // QKV projections + RoPE; V epilogue writes transposed+split g_Vts directly
    mma_gemm_kernel<<<dim3(DMODEL / 128, MROWS / 128, 3), 256, DYN_GEMM>>>(
        pos, nullptr, -1);
    // Causal flash attention (3xBF16), LPT order: x = bh, y = q-tile (reversed)
    attn_mma_kernel<<<dim3(BATCH * NHEADS, S_LEN / 128), 256, DYN_ATTN>>>();
    // Output projection (3xBF16)
    mma_gemm_kernel<<<dim3(DMODEL / 128, MROWS / 128, 1), 256, DYN_GEMM>>>(
        pos, out, 3);
}